// round 14
// baseline (speedup 1.0000x reference)
#include <cuda_runtime.h>
#include <math.h>
#include <stdint.h>

#define Bn   16
#define Cn   768
#define Sn   729
#define Hn   8
#define Dn   96
#define En   3
#define HIDn 3072
#define NTOK (Bn*Sn)            /* 11664 tokens */
#define PERMSZ (NTOK + 128*En)  /* padded routing buffer */

// ---------------- static scratch (no allocation allowed) ----------------
__device__ float g_tok   [NTOK*Cn];                 // LN'd tokens [t, c]
__device__ float g_qkv   [(size_t)NTOK*3*Cn];       // [t, 3*C]
__device__ float g_scores[(size_t)Bn*Hn*Sn*Sn];     // attention logits/probs
__device__ float g_ctx   [NTOK*Cn];                 // attention context [t, c]
__device__ float g_tok2  [NTOK*Cn];                 // x2 tokens [t, c]
__device__ float g_h1    [(size_t)PERMSZ*HIDn];     // expert hidden
__device__ float g_mg    [NTOK];
__device__ int   g_eid   [NTOK];
__device__ float g_gscale[NTOK];
__device__ float g_denom [Sn*En];
__device__ int   g_perm  [PERMSZ];
__device__ int   g_count [En];
__device__ int   g_seg   [En+1];
__device__ int   g_pos   [En];
__device__ double g_part [Bn*64*2];
__device__ float g_mu[Bn], g_rsig[Bn];

// ---------------- LayerNorm stats ----------------
__global__ void ln_partial(const float* __restrict__ x) {
    int b = blockIdx.y, p = blockIdx.x;
    const int N = Cn*Sn;
    const int chunk = N / 64;
    const float* xb = x + (size_t)b*N;
    double s = 0.0, ss = 0.0;
    for (int i = p*chunk + threadIdx.x; i < (p+1)*chunk; i += 256) {
        float v = xb[i];
        s += v; ss += (double)v*v;
    }
    __shared__ double sh[256], sh2[256];
    sh[threadIdx.x] = s; sh2[threadIdx.x] = ss;
    __syncthreads();
    for (int o = 128; o > 0; o >>= 1) {
        if (threadIdx.x < o) { sh[threadIdx.x] += sh[threadIdx.x+o]; sh2[threadIdx.x] += sh2[threadIdx.x+o]; }
        __syncthreads();
    }
    if (threadIdx.x == 0) {
        g_part[(b*64+p)*2]   = sh[0];
        g_part[(b*64+p)*2+1] = sh2[0];
    }
}

__global__ void ln_final() {
    int b = blockIdx.x;
    __shared__ double sh[64], sh2[64];
    sh[threadIdx.x]  = g_part[(b*64+threadIdx.x)*2];
    sh2[threadIdx.x] = g_part[(b*64+threadIdx.x)*2+1];
    __syncthreads();
    for (int o = 32; o > 0; o >>= 1) {
        if (threadIdx.x < o) { sh[threadIdx.x] += sh[threadIdx.x+o]; sh2[threadIdx.x] += sh2[threadIdx.x+o]; }
        __syncthreads();
    }
    if (threadIdx.x == 0) {
        double N  = (double)(Cn*Sn);
        double mu = sh[0]/N;
        double var = sh2[0]/N - mu*mu;
        g_mu[b]   = (float)mu;
        g_rsig[b] = (float)(1.0/sqrt(var + 1e-5));
    }
}

// normalize + affine + transpose [b,c,s] -> token-major [t,c] via 32x32 smem tiles
__global__ void build_tok(const float* __restrict__ x,
                          const float* __restrict__ gamma,
                          const float* __restrict__ beta) {
    __shared__ float tx_[32][33], tg[32][33], tb[32][33];
    int b  = blockIdx.z;
    int c0 = blockIdx.y * 32;
    int s0 = blockIdx.x * 32;
    int li = threadIdx.x & 31;
    int lj = threadIdx.x >> 5;
    #pragma unroll
    for (int r = 0; r < 4; r++) {
        int c = c0 + lj + r*8;
        int s = s0 + li;
        bool ok = (s < Sn);
        size_t xi = ((size_t)b*Cn + c)*Sn + s;
        size_t gi = (size_t)c*Sn + s;
        tx_[lj + r*8][li] = ok ? x[xi] : 0.f;
        tg [lj + r*8][li] = ok ? gamma[gi] : 0.f;
        tb [lj + r*8][li] = ok ? beta[gi]  : 0.f;
    }
    __syncthreads();
    float mu = g_mu[b], rs = g_rsig[b];
    #pragma unroll
    for (int r = 0; r < 4; r++) {
        int s = s0 + lj + r*8;
        int c = c0 + li;
        if (s < Sn) {
            float v = (tx_[li][lj + r*8] - mu) * rs * tg[li][lj + r*8] + tb[li][lj + r*8];
            g_tok[(size_t)(b*Sn + s)*Cn + c] = v;
        }
    }
}

// ---------------- tf32 helpers ----------------
__device__ __forceinline__ void split_tf(float x, uint32_t& hi, uint32_t& lo) {
    asm("cvt.rna.tf32.f32 %0, %1;" : "=r"(hi) : "f"(x));
    float res = x - __uint_as_float(hi);
    asm("cvt.rna.tf32.f32 %0, %1;" : "=r"(lo) : "f"(res));
}
__device__ __forceinline__ void mma8(float* c, const uint32_t* a, const uint32_t* b) {
    asm volatile(
        "mma.sync.aligned.m16n8k8.row.col.f32.tf32.tf32.f32 "
        "{%0,%1,%2,%3}, {%4,%5,%6,%7}, {%8,%9}, {%0,%1,%2,%3};"
        : "+f"(c[0]), "+f"(c[1]), "+f"(c[2]), "+f"(c[3])
        : "r"(a[0]), "r"(a[1]), "r"(a[2]), "r"(a[3]), "r"(b[0]), "r"(b[1]));
}

// ------ tensor-core GEMM tile: 128x64 block, 8 warps (32x32 each), 3xTF32 -----
// (hi,lo) interleaved as uint2 in SMEM (pre-split once per element):
//   A stored [m][k], row = 20 uint2 (20%16=4 -> conflict-free frag loads & stores)
//   B stored [k][n], row = 68 uint2 (68%16=4 -> conflict-free frag loads & stores)
// Inner loop: pure LDS.64 + HMMA, zero cvt.
template<class FA, class FB, class FC>
__device__ __forceinline__ void gemm_tc(int M, int N, int K, int m0, int n0,
                                        FA fa, FB fb, FC fc) {
    constexpr int BM = 128, BN = 64, BK = 16, NTHR = 256;
    constexpr int AS = BK + 4;   // 20
    constexpr int BS = BN + 4;   // 68
    __shared__ uint2 As[BM][AS];
    __shared__ uint2 Bs[BK][BS];
    const int tid  = threadIdx.x;
    const int wid  = tid >> 5;
    const int lane = tid & 31;
    const int mw = wid >> 1;          // 0..3 -> m base mw*32
    const int nw = wid & 1;           // 0..1 -> n base nw*32
    const int r    = lane >> 2;       // 0..7
    const int cg   = lane & 3;        // 0..3

    constexpr int AE = BM*BK/NTHR;    // 8
    constexpr int BE = BN*BK/NTHR;    // 4
    float ra[AE], rb[BE];

    auto loadA = [&](int k0) {
        #pragma unroll
        for (int i = 0; i < AE; i++) {
            int idx = tid + i*NTHR;
            int m = idx >> 4, k = idx & 15;       // consecutive tid -> consecutive k (coalesced)
            bool ok = (m0+m) < M && (k0+k) < K;
            ra[i] = ok ? fa(m0+m, k0+k) : 0.f;
        }
    };
    auto loadB = [&](int k0) {
        #pragma unroll
        for (int i = 0; i < BE; i++) {
            int idx = tid + i*NTHR;
            int k = idx >> 6, n = idx & 63;       // consecutive tid -> consecutive n (coalesced)
            bool ok = (n0+n) < N && (k0+k) < K;
            rb[i] = ok ? fb(k0+k, n0+n) : 0.f;
        }
    };
    auto storeAB = [&]() {
        #pragma unroll
        for (int i = 0; i < AE; i++) {
            int idx = tid + i*NTHR;
            int m = idx >> 4, k = idx & 15;
            uint32_t h, l; split_tf(ra[i], h, l);
            As[m][k] = make_uint2(h, l);
        }
        #pragma unroll
        for (int i = 0; i < BE; i++) {
            int idx = tid + i*NTHR;
            int k = idx >> 6, n = idx & 63;
            uint32_t h, l; split_tf(rb[i], h, l);
            Bs[k][n] = make_uint2(h, l);
        }
    };

    float acc[2][4][4];
    #pragma unroll
    for (int i = 0; i < 2; i++)
        #pragma unroll
        for (int j = 0; j < 4; j++)
            #pragma unroll
            for (int q = 0; q < 4; q++) acc[i][j][q] = 0.f;

    loadA(0); loadB(0);
    for (int k0 = 0; k0 < K; k0 += BK) {
        storeAB();
        __syncthreads();
        if (k0 + BK < K) { loadA(k0 + BK); loadB(k0 + BK); }
        #pragma unroll
        for (int ks = 0; ks < BK; ks += 8) {
            uint32_t aH[2][4], aL[2][4], bH[4][2], bL[4][2];
            #pragma unroll
            for (int i = 0; i < 2; i++) {
                int mb = mw*32 + i*16;
                uint2 v0 = As[mb + r    ][ks + cg    ];
                uint2 v1 = As[mb + r + 8][ks + cg    ];
                uint2 v2 = As[mb + r    ][ks + cg + 4];
                uint2 v3 = As[mb + r + 8][ks + cg + 4];
                aH[i][0] = v0.x; aL[i][0] = v0.y;
                aH[i][1] = v1.x; aL[i][1] = v1.y;
                aH[i][2] = v2.x; aL[i][2] = v2.y;
                aH[i][3] = v3.x; aL[i][3] = v3.y;
            }
            #pragma unroll
            for (int j = 0; j < 4; j++) {
                int nb = nw*32 + j*8;
                uint2 w0 = Bs[ks + cg    ][nb + r];
                uint2 w1 = Bs[ks + cg + 4][nb + r];
                bH[j][0] = w0.x; bL[j][0] = w0.y;
                bH[j][1] = w1.x; bL[j][1] = w1.y;
            }
            #pragma unroll
            for (int i = 0; i < 2; i++)
                #pragma unroll
                for (int j = 0; j < 4; j++) {
                    mma8(acc[i][j], aL[i], bH[j]);
                    mma8(acc[i][j], aH[i], bL[j]);
                    mma8(acc[i][j], aH[i], bH[j]);
                }
        }
        __syncthreads();
    }
    #pragma unroll
    for (int i = 0; i < 2; i++) {
        #pragma unroll
        for (int j = 0; j < 4; j++) {
            int mA = m0 + mw*32 + i*16 + r;
            int nA = n0 + nw*32 + j*8 + cg*2;
            if (mA < M) {
                if (nA   < N) fc(mA, nA,   acc[i][j][0]);
                if (nA+1 < N) fc(mA, nA+1, acc[i][j][1]);
            }
            if (mA + 8 < M) {
                if (nA   < N) fc(mA+8, nA,   acc[i][j][2]);
                if (nA+1 < N) fc(mA+8, nA+1, acc[i][j][3]);
            }
        }
    }
}

// ---------------- attention ----------------
__global__ void __launch_bounds__(256, 2) k_gemm_qkv(const float* __restrict__ w) {
    gemm_tc(NTOK, 3*Cn, Cn, blockIdx.y*128, blockIdx.x*64,
        [&] (int m, int k) { return g_tok[(size_t)m*Cn + k]; },
        [&] (int k, int n) { return w[(size_t)k*3*Cn + n]; },
        [&] (int m, int n, float v) { g_qkv[(size_t)m*3*Cn + n] = v; });
}

__global__ void __launch_bounds__(256, 2) k_gemm_scores() {
    int z = blockIdx.z, bI = z >> 3, h = z & 7;
    const float* qb = g_qkv + (size_t)bI*Sn*(3*Cn) + h*Dn;
    const float* kb = qb + Cn;
    float* out = g_scores + (size_t)z*Sn*Sn;
    gemm_tc(Sn, Sn, Dn, blockIdx.y*128, blockIdx.x*64,
        [&] (int m, int k) { return qb[(size_t)m*(3*Cn) + k]; },
        [&] (int k, int n) { return kb[(size_t)n*(3*Cn) + k]; },
        [&] (int m, int n, float v) { out[m*Sn + n] = v; });
}

__global__ void k_softmax() {
    float* p = g_scores + (size_t)blockIdx.x*Sn;
    int tid = threadIdx.x;
    __shared__ float red[128];
    float mx = -1e30f;
    for (int i = tid; i < Sn; i += 128) mx = fmaxf(mx, p[i]);
    red[tid] = mx; __syncthreads();
    for (int o = 64; o > 0; o >>= 1) { if (tid < o) red[tid] = fmaxf(red[tid], red[tid+o]); __syncthreads(); }
    mx = red[0]; __syncthreads();
    float s = 0.f;
    for (int i = tid; i < Sn; i += 128) { float e = __expf(p[i]-mx); p[i] = e; s += e; }
    red[tid] = s; __syncthreads();
    for (int o = 64; o > 0; o >>= 1) { if (tid < o) red[tid] += red[tid+o]; __syncthreads(); }
    float inv = 1.f/red[0];
    for (int i = tid; i < Sn; i += 128) p[i] *= inv;
}

__global__ void __launch_bounds__(256, 2) k_gemm_ctx() {
    int z = blockIdx.z, bI = z >> 3, h = z & 7;
    const float* att = g_scores + (size_t)z*Sn*Sn;
    const float* vb  = g_qkv + (size_t)bI*Sn*(3*Cn) + 2*Cn + h*Dn;
    gemm_tc(Sn, Dn, Sn, blockIdx.y*128, blockIdx.x*64,
        [&] (int m, int k) { return att[(size_t)m*Sn + k]; },
        [&] (int k, int n) { return vb[(size_t)k*(3*Cn) + n]; },
        [&] (int m, int n, float v) {
            g_ctx[((size_t)(bI*Sn + m))*Cn + h*Dn + n] = v;
        });
}

// out-proj + residual: writes tok2 (token-major) and out = x2 ([b,c,s])
__global__ void __launch_bounds__(256, 2) k_gemm_wout(const float* __restrict__ w,
                            const float* __restrict__ x,
                            float* __restrict__ out) {
    gemm_tc(NTOK, Cn, Cn, blockIdx.y*128, blockIdx.x*64,
        [&] (int m, int k) { return g_ctx[(size_t)m*Cn + k]; },
        [&] (int k, int n) { return w[(size_t)k*Cn + n]; },
        [&] (int m, int n, float v) {
            int b = m / Sn, s = m % Sn;
            size_t oi = ((size_t)b*Cn + n)*Sn + s;
            float x2 = x[oi] + v;
            g_tok2[(size_t)m*Cn + n] = x2;
            out[oi] = x2;
        });
}

// ---------------- MoE gate + routing ----------------
__global__ void k_gate(const float* __restrict__ wg, const float* __restrict__ bg) {
    int warp = (blockIdx.x*128 + threadIdx.x) >> 5;
    int lane = threadIdx.x & 31;
    if (warp >= NTOK) return;
    const float* row = g_tok2 + (size_t)warp*Cn;
    float a0 = 0.f, a1 = 0.f, a2 = 0.f;
    for (int c = lane; c < Cn; c += 32) {
        float t = row[c];
        a0 = fmaf(t, wg[c*3+0], a0);
        a1 = fmaf(t, wg[c*3+1], a1);
        a2 = fmaf(t, wg[c*3+2], a2);
    }
    for (int o = 16; o > 0; o >>= 1) {
        a0 += __shfl_down_sync(0xffffffffu, a0, o);
        a1 += __shfl_down_sync(0xffffffffu, a1, o);
        a2 += __shfl_down_sync(0xffffffffu, a2, o);
    }
    if (lane == 0) {
        a0 += bg[0]; a1 += bg[1]; a2 += bg[2];
        int e = 0; float best = a0;
        if (a1 > best) { best = a1; e = 1; }
        if (a2 > best) { best = a2; e = 2; }
        float e0 = __expf(a0-best), e1 = __expf(a1-best), e2 = __expf(a2-best);
        float sum = e0 + e1 + e2;
        float pe = (e == 0 ? e0 : (e == 1 ? e1 : e2)) / sum;
        g_eid[warp] = e; g_mg[warp] = pe;
    }
}

__global__ void k_denom() {
    int i = blockIdx.x*128 + threadIdx.x;
    if (i >= Sn*En) return;
    int s = i / En, e = i % En;
    float acc = 0.f;
    for (int b = 0; b < Bn; b++) { int t = b*Sn + s; if (g_eid[t] == e) acc += g_mg[t]; }
    g_denom[i] = acc + 1e-6f;
}

__global__ void k_scale() {
    int t = blockIdx.x*256 + threadIdx.x;
    if (t >= NTOK) return;
    int s = t % Sn;
    g_gscale[t] = g_mg[t] / g_denom[s*En + g_eid[t]] * (float)Bn;
}

__global__ void k_rinit() {
    int i = blockIdx.x*256 + threadIdx.x;
    if (i < PERMSZ) g_perm[i] = -1;
    if (i < En) { g_count[i] = 0; g_pos[i] = 0; }
}
__global__ void k_rcount() {
    int t = blockIdx.x*256 + threadIdx.x;
    if (t < NTOK) atomicAdd(&g_count[g_eid[t]], 1);
}
__global__ void k_roffs() {
    int a = 0;
    for (int e = 0; e < En; e++) { g_seg[e] = a; a += (g_count[e] + 127) & ~127; }
    g_seg[En] = a;
}
__global__ void k_rscatter() {
    int t = blockIdx.x*256 + threadIdx.x;
    if (t >= NTOK) return;
    int e = g_eid[t];
    int p = atomicAdd(&g_pos[e], 1);
    g_perm[g_seg[e] + p] = t;
}

// ---------------- routed expert FFN ----------------
__global__ void __launch_bounds__(256, 2) k_ffn1(const float* __restrict__ w1, const float* __restrict__ b1) {
    int e = blockIdx.z;
    int cnt = g_count[e];
    int m0 = blockIdx.y*128;
    if (m0 >= cnt) return;
    int base = g_seg[e];
    const float* W = w1 + (size_t)e*Cn*HIDn;
    const float* bias = b1 + e*HIDn;
    gemm_tc(cnt, HIDn, Cn, m0, blockIdx.x*64,
        [&] (int m, int k) { return g_tok2[(size_t)g_perm[base+m]*Cn + k]; },
        [&] (int k, int n) { return W[(size_t)k*HIDn + n]; },
        [&] (int m, int n, float v) {
            float u = v + bias[n];
            g_h1[(size_t)(base+m)*HIDn + n] = 0.5f*u*(1.f + erff(u*0.70710678118654752f));
        });
}

__global__ void __launch_bounds__(256, 2) k_ffn2(const float* __restrict__ w2, const float* __restrict__ b2,
                       float* __restrict__ out) {
    int e = blockIdx.z;
    int cnt = g_count[e];
    int m0 = blockIdx.y*128;
    if (m0 >= cnt) return;
    int base = g_seg[e];
    const float* W = w2 + (size_t)e*HIDn*Cn;
    const float* bias = b2 + e*Cn;
    gemm_tc(cnt, Cn, HIDn, m0, blockIdx.x*64,
        [&] (int m, int k) { return g_h1[(size_t)(base+m)*HIDn + k]; },
        [&] (int k, int n) { return W[(size_t)k*Cn + n]; },
        [&] (int m, int n, float v) {
            int t = g_perm[base+m];
            float g = g_gscale[t];
            int b = t / Sn, s = t % Sn;
            size_t oi = ((size_t)b*Cn + n)*Sn + s;
            out[oi] += g * (v + bias[n]);
        });
}

// ---------------- launch ----------------
extern "C" void kernel_launch(void* const* d_in, const int* in_sizes, int n_in,
                              void* d_out, int out_size) {
    (void)in_sizes; (void)n_in; (void)out_size;
    const float* x      = (const float*)d_in[0];
    const float* gamma  = (const float*)d_in[1];
    const float* beta   = (const float*)d_in[2];
    const float* w_qkv  = (const float*)d_in[3];
    const float* w_out  = (const float*)d_in[4];
    const float* w_gate = (const float*)d_in[5];
    const float* b_gate = (const float*)d_in[6];
    const float* w1     = (const float*)d_in[7];
    const float* b1     = (const float*)d_in[8];
    const float* w2     = (const float*)d_in[9];
    const float* b2     = (const float*)d_in[10];
    float* out = (float*)d_out;

    ln_partial<<<dim3(64, Bn), 256>>>(x);
    ln_final<<<Bn, 64>>>();
    build_tok<<<dim3((Sn+31)/32, Cn/32, Bn), 256>>>(x, gamma, beta);

    k_gemm_qkv<<<dim3((3*Cn)/64, (NTOK+127)/128), 256>>>(w_qkv);        // 36 x 92
    k_gemm_scores<<<dim3(12, 6, Bn*Hn), 256>>>();
    k_softmax<<<Bn*Hn*Sn, 128>>>();
    k_gemm_ctx<<<dim3(2, 6, Bn*Hn), 256>>>();
    k_gemm_wout<<<dim3(Cn/64, (NTOK+127)/128), 256>>>(w_out, x, out);   // 12 x 92

    k_gate<<<(NTOK + 3)/4, 128>>>(w_gate, b_gate);
    k_denom<<<(Sn*En + 127)/128, 128>>>();
    k_scale<<<(NTOK + 255)/256, 256>>>();
    k_rinit<<<(PERMSZ + 255)/256, 256>>>();
    k_rcount<<<(NTOK + 255)/256, 256>>>();
    k_roffs<<<1, 1>>>();
    k_rscatter<<<(NTOK + 255)/256, 256>>>();

    k_ffn1<<<dim3(HIDn/64, (NTOK+127)/128, En), 256>>>(w1, b1);         // 48 x 92 x 3
    k_ffn2<<<dim3(Cn/64, (NTOK+127)/128, En), 256>>>(w2, b2, out);      // 12 x 92 x 3
}

// round 15
// speedup vs baseline: 1.3430x; 1.3430x over previous
#include <cuda_runtime.h>
#include <cuda_bf16.h>
#include <math.h>
#include <stdint.h>

#define Bn   16
#define Cn   768
#define Sn   729
#define Hn   8
#define Dn   96
#define En   3
#define HIDn 3072
#define NTOK (Bn*Sn)            /* 11664 tokens */
#define PERMSZ (NTOK + 128*En)  /* padded routing buffer */

// ---------------- static scratch (no allocation allowed) ----------------
__device__ float g_tok   [NTOK*Cn];                 // LN'd tokens [t, c]
__device__ float g_qkv   [(size_t)NTOK*3*Cn];       // [t, 3*C]
__device__ float g_scores[(size_t)Bn*Hn*Sn*Sn];     // attention logits/probs
__device__ float g_ctx   [NTOK*Cn];                 // attention context [t, c]
__device__ float g_tok2  [NTOK*Cn];                 // x2 tokens [t, c]
__device__ float g_h1    [(size_t)PERMSZ*HIDn];     // expert hidden
__device__ float g_mg    [NTOK];
__device__ int   g_eid   [NTOK];
__device__ float g_gscale[NTOK];
__device__ float g_denom [Sn*En];
__device__ int   g_perm  [PERMSZ];
__device__ int   g_count [En];
__device__ int   g_seg   [En+1];
__device__ int   g_pos   [En];
__device__ double g_part [Bn*64*2];
__device__ float g_mu[Bn], g_rsig[Bn];

// ---------------- LayerNorm stats ----------------
__global__ void ln_partial(const float* __restrict__ x) {
    int b = blockIdx.y, p = blockIdx.x;
    const int N = Cn*Sn;
    const int chunk = N / 64;
    const float* xb = x + (size_t)b*N;
    double s = 0.0, ss = 0.0;
    for (int i = p*chunk + threadIdx.x; i < (p+1)*chunk; i += 256) {
        float v = xb[i];
        s += v; ss += (double)v*v;
    }
    __shared__ double sh[256], sh2[256];
    sh[threadIdx.x] = s; sh2[threadIdx.x] = ss;
    __syncthreads();
    for (int o = 128; o > 0; o >>= 1) {
        if (threadIdx.x < o) { sh[threadIdx.x] += sh[threadIdx.x+o]; sh2[threadIdx.x] += sh2[threadIdx.x+o]; }
        __syncthreads();
    }
    if (threadIdx.x == 0) {
        g_part[(b*64+p)*2]   = sh[0];
        g_part[(b*64+p)*2+1] = sh2[0];
    }
}

__global__ void ln_final() {
    int b = blockIdx.x;
    __shared__ double sh[64], sh2[64];
    sh[threadIdx.x]  = g_part[(b*64+threadIdx.x)*2];
    sh2[threadIdx.x] = g_part[(b*64+threadIdx.x)*2+1];
    __syncthreads();
    for (int o = 32; o > 0; o >>= 1) {
        if (threadIdx.x < o) { sh[threadIdx.x] += sh[threadIdx.x+o]; sh2[threadIdx.x] += sh2[threadIdx.x+o]; }
        __syncthreads();
    }
    if (threadIdx.x == 0) {
        double N  = (double)(Cn*Sn);
        double mu = sh[0]/N;
        double var = sh2[0]/N - mu*mu;
        g_mu[b]   = (float)mu;
        g_rsig[b] = (float)(1.0/sqrt(var + 1e-5));
    }
}

// normalize + affine + transpose [b,c,s] -> token-major [t,c] via 32x32 smem tiles
__global__ void build_tok(const float* __restrict__ x,
                          const float* __restrict__ gamma,
                          const float* __restrict__ beta) {
    __shared__ float tx_[32][33], tg[32][33], tb[32][33];
    int b  = blockIdx.z;
    int c0 = blockIdx.y * 32;
    int s0 = blockIdx.x * 32;
    int li = threadIdx.x & 31;
    int lj = threadIdx.x >> 5;
    #pragma unroll
    for (int r = 0; r < 4; r++) {
        int c = c0 + lj + r*8;
        int s = s0 + li;
        bool ok = (s < Sn);
        size_t xi = ((size_t)b*Cn + c)*Sn + s;
        size_t gi = (size_t)c*Sn + s;
        tx_[lj + r*8][li] = ok ? x[xi] : 0.f;
        tg [lj + r*8][li] = ok ? gamma[gi] : 0.f;
        tb [lj + r*8][li] = ok ? beta[gi]  : 0.f;
    }
    __syncthreads();
    float mu = g_mu[b], rs = g_rsig[b];
    #pragma unroll
    for (int r = 0; r < 4; r++) {
        int s = s0 + lj + r*8;
        int c = c0 + li;
        if (s < Sn) {
            float v = (tx_[li][lj + r*8] - mu) * rs * tg[li][lj + r*8] + tb[li][lj + r*8];
            g_tok[(size_t)(b*Sn + s)*Cn + c] = v;
        }
    }
}

// ---------------- tf32 helpers ----------------
__device__ __forceinline__ uint32_t f2tf(float x) {
    uint32_t r;
    asm("cvt.rna.tf32.f32 %0, %1;" : "=r"(r) : "f"(x));
    return r;
}
__device__ __forceinline__ void split_tf(float x, uint32_t& hi, uint32_t& lo) {
    asm("cvt.rna.tf32.f32 %0, %1;" : "=r"(hi) : "f"(x));
    float res = x - __uint_as_float(hi);
    asm("cvt.rna.tf32.f32 %0, %1;" : "=r"(lo) : "f"(res));
}
__device__ __forceinline__ void mma8(float* c, const uint32_t* a, const uint32_t* b) {
    asm volatile(
        "mma.sync.aligned.m16n8k8.row.col.f32.tf32.tf32.f32 "
        "{%0,%1,%2,%3}, {%4,%5,%6,%7}, {%8,%9}, {%0,%1,%2,%3};"
        : "+f"(c[0]), "+f"(c[1]), "+f"(c[2]), "+f"(c[3])
        : "r"(a[0]), "r"(a[1]), "r"(a[2]), "r"(a[3]), "r"(b[0]), "r"(b[1]));
}

// ---------------- bf16 helpers ----------------
// pack (lo half = x at even k, hi half = y at odd k)
__device__ __forceinline__ uint32_t pack_bf16(float x, float y) {
    uint32_t r;
    asm("cvt.rn.bf16x2.f32 %0, %1, %2;" : "=r"(r) : "f"(y), "f"(x));
    return r;
}
// split pair (f0,f1) -> hi-pair + lo-pair (residuals)
__device__ __forceinline__ void split_bf2(float f0, float f1, uint32_t& hp, uint32_t& lp) {
    hp = pack_bf16(f0, f1);
    float h0 = __uint_as_float(hp << 16);
    float h1 = __uint_as_float(hp & 0xffff0000u);
    lp = pack_bf16(f0 - h0, f1 - h1);
}
__device__ __forceinline__ void mma16(float* c, const uint32_t* a, const uint32_t* b) {
    asm volatile(
        "mma.sync.aligned.m16n8k16.row.col.f32.bf16.bf16.f32 "
        "{%0,%1,%2,%3}, {%4,%5,%6,%7}, {%8,%9}, {%0,%1,%2,%3};"
        : "+f"(c[0]), "+f"(c[1]), "+f"(c[2]), "+f"(c[3])
        : "r"(a[0]), "r"(a[1]), "r"(a[2]), "r"(a[3]), "r"(b[0]), "r"(b[1]));
}

// ---- tensor-core GEMM tile (3xTF32): 128x64 block, 8 warps (32x32) — R5 best ----
template<class FA, class FB, class FC>
__device__ __forceinline__ void gemm_tc(int M, int N, int K, int m0, int n0,
                                        FA fa, FB fb, FC fc) {
    constexpr int BM = 128, BN = 64, BK = 16, NTHR = 256;
    __shared__ float As[BK][BM + 8];
    __shared__ float Bs[BK][BN + 8];
    const int tid  = threadIdx.x;
    const int wid  = tid >> 5;
    const int lane = tid & 31;
    const int mw = wid >> 1;
    const int nw = wid & 1;
    const int r    = lane >> 2;
    const int cg   = lane & 3;

    constexpr int AE = BM*BK/NTHR;    // 8
    constexpr int BE = BN*BK/NTHR;    // 4
    float ra[AE], rb[BE];

    auto loadA = [&](int k0) {
        #pragma unroll
        for (int i = 0; i < AE; i++) {
            int idx = tid + i*NTHR;
            int m = idx / BK, k = idx % BK;
            bool ok = (m0+m) < M && (k0+k) < K;
            ra[i] = ok ? fa(m0+m, k0+k) : 0.f;
        }
    };
    auto loadB = [&](int k0) {
        #pragma unroll
        for (int i = 0; i < BE; i++) {
            int idx = tid + i*NTHR;
            int k = idx / BN, n = idx % BN;
            bool ok = (n0+n) < N && (k0+k) < K;
            rb[i] = ok ? fb(k0+k, n0+n) : 0.f;
        }
    };
    auto storeAB = [&]() {
        #pragma unroll
        for (int i = 0; i < AE; i++) {
            int idx = tid + i*NTHR;
            As[idx % BK][idx / BK] = ra[i];
        }
        #pragma unroll
        for (int i = 0; i < BE; i++) {
            int idx = tid + i*NTHR;
            Bs[idx / BN][idx % BN] = rb[i];
        }
    };

    float acc[2][4][4];
    #pragma unroll
    for (int i = 0; i < 2; i++)
        #pragma unroll
        for (int j = 0; j < 4; j++)
            #pragma unroll
            for (int q = 0; q < 4; q++) acc[i][j][q] = 0.f;

    loadA(0); loadB(0);
    for (int k0 = 0; k0 < K; k0 += BK) {
        storeAB();
        __syncthreads();
        if (k0 + BK < K) { loadA(k0 + BK); loadB(k0 + BK); }
        #pragma unroll
        for (int ks = 0; ks < BK; ks += 8) {
            uint32_t aH[2][4], aL[2][4], bH[4][2], bL[4][2];
            #pragma unroll
            for (int i = 0; i < 2; i++) {
                int mb = mw*32 + i*16;
                float v0 = As[ks + cg    ][mb + r    ];
                float v1 = As[ks + cg    ][mb + r + 8];
                float v2 = As[ks + cg + 4][mb + r    ];
                float v3 = As[ks + cg + 4][mb + r + 8];
                split_tf(v0, aH[i][0], aL[i][0]);
                split_tf(v1, aH[i][1], aL[i][1]);
                split_tf(v2, aH[i][2], aL[i][2]);
                split_tf(v3, aH[i][3], aL[i][3]);
            }
            #pragma unroll
            for (int j = 0; j < 4; j++) {
                int nb = nw*32 + j*8;
                float v0 = Bs[ks + cg    ][nb + r];
                float v1 = Bs[ks + cg + 4][nb + r];
                split_tf(v0, bH[j][0], bL[j][0]);
                split_tf(v1, bH[j][1], bL[j][1]);
            }
            #pragma unroll
            for (int i = 0; i < 2; i++)
                #pragma unroll
                for (int j = 0; j < 4; j++) {
                    mma8(acc[i][j], aL[i], bH[j]);
                    mma8(acc[i][j], aH[i], bL[j]);
                    mma8(acc[i][j], aH[i], bH[j]);
                }
        }
        __syncthreads();
    }
    #pragma unroll
    for (int i = 0; i < 2; i++) {
        #pragma unroll
        for (int j = 0; j < 4; j++) {
            int mA = m0 + mw*32 + i*16 + r;
            int nA = n0 + nw*32 + j*8 + cg*2;
            if (mA < M) {
                if (nA   < N) fc(mA, nA,   acc[i][j][0]);
                if (nA+1 < N) fc(mA, nA+1, acc[i][j][1]);
            }
            if (mA + 8 < M) {
                if (nA   < N) fc(mA+8, nA,   acc[i][j][2]);
                if (nA+1 < N) fc(mA+8, nA+1, acc[i][j][3]);
            }
        }
    }
}

// ---- bf16 3-term GEMM tile: 128x64 block, 8 warps (32x32), mma.m16n8k16 ----
// A/B pre-split to (hi,lo) packed-bf16x2 pairs in SMEM; half the MMA instrs of tf32 path.
template<class FA, class FB, class FC>
__device__ __forceinline__ void gemm_bf(int M, int N, int K, int m0, int n0,
                                        FA fa, FB fb, FC fc) {
    constexpr int BM = 128, BN = 64, BK = 16, NTHR = 256;
    constexpr int K2 = BK/2;                 // 8 packed k-pairs
    __shared__ uint2 As[BM][K2 + 4];         // stride 12 uint2 = 24 words (conflict-free loads)
    __shared__ uint2 Bs[K2][BN + 4];         // stride 68 uint2 = 136 words (conflict-free loads)
    const int tid  = threadIdx.x;
    const int wid  = tid >> 5;
    const int lane = tid & 31;
    const int mw = wid >> 1;          // m base mw*32
    const int nw = wid & 1;           // n base nw*32
    const int r    = lane >> 2;       // 0..7
    const int cg   = lane & 3;        // 0..3

    constexpr int AE = BM*K2/NTHR;    // 4 pairs
    constexpr int BE = K2*BN/NTHR;    // 2 pairs
    float raf[AE][2], rbf[BE][2];

    auto loadA = [&](int k0) {
        #pragma unroll
        for (int i = 0; i < AE; i++) {
            int idx = tid + i*NTHR;
            int m = idx >> 3, k2 = idx & 7;
            int k = k0 + 2*k2;
            bool okm = (m0+m) < M;
            raf[i][0] = (okm && k   < K) ? fa(m0+m, k  ) : 0.f;
            raf[i][1] = (okm && k+1 < K) ? fa(m0+m, k+1) : 0.f;
        }
    };
    auto loadB = [&](int k0) {
        #pragma unroll
        for (int i = 0; i < BE; i++) {
            int idx = tid + i*NTHR;
            int k2 = idx >> 6, n = idx & 63;
            int k = k0 + 2*k2;
            bool okn = (n0+n) < N;
            rbf[i][0] = (okn && k   < K) ? fb(k,   n0+n) : 0.f;
            rbf[i][1] = (okn && k+1 < K) ? fb(k+1, n0+n) : 0.f;
        }
    };
    auto storeAB = [&]() {
        #pragma unroll
        for (int i = 0; i < AE; i++) {
            int idx = tid + i*NTHR;
            int m = idx >> 3, k2 = idx & 7;
            uint32_t hp, lp; split_bf2(raf[i][0], raf[i][1], hp, lp);
            As[m][k2] = make_uint2(hp, lp);
        }
        #pragma unroll
        for (int i = 0; i < BE; i++) {
            int idx = tid + i*NTHR;
            int k2 = idx >> 6, n = idx & 63;
            uint32_t hp, lp; split_bf2(rbf[i][0], rbf[i][1], hp, lp);
            Bs[k2][n] = make_uint2(hp, lp);
        }
    };

    float acc[2][4][4];
    #pragma unroll
    for (int i = 0; i < 2; i++)
        #pragma unroll
        for (int j = 0; j < 4; j++)
            #pragma unroll
            for (int q = 0; q < 4; q++) acc[i][j][q] = 0.f;

    loadA(0); loadB(0);
    for (int k0 = 0; k0 < K; k0 += BK) {
        storeAB();
        __syncthreads();
        if (k0 + BK < K) { loadA(k0 + BK); loadB(k0 + BK); }
        // one m16n8k16 step covers the whole BK=16 slab
        uint32_t aH[2][4], aL[2][4], bH[4][2], bL[4][2];
        #pragma unroll
        for (int i = 0; i < 2; i++) {
            int mb = mw*32 + i*16;
            uint2 v0 = As[mb + r    ][cg    ];   // a0: (r,   k=2cg..2cg+1)
            uint2 v1 = As[mb + r + 8][cg    ];   // a1: (r+8, same)
            uint2 v2 = As[mb + r    ][cg + 4];   // a2: (r,   k=2cg+8..9)
            uint2 v3 = As[mb + r + 8][cg + 4];   // a3: (r+8, same)
            aH[i][0] = v0.x; aL[i][0] = v0.y;
            aH[i][1] = v1.x; aL[i][1] = v1.y;
            aH[i][2] = v2.x; aL[i][2] = v2.y;
            aH[i][3] = v3.x; aL[i][3] = v3.y;
        }
        #pragma unroll
        for (int j = 0; j < 4; j++) {
            int nb = nw*32 + j*8;
            uint2 w0 = Bs[cg    ][nb + r];       // b0: (k=2cg..2cg+1,  n=r)
            uint2 w1 = Bs[cg + 4][nb + r];       // b1: (k=2cg+8..9,    n=r)
            bH[j][0] = w0.x; bL[j][0] = w0.y;
            bH[j][1] = w1.x; bL[j][1] = w1.y;
        }
        #pragma unroll
        for (int i = 0; i < 2; i++)
            #pragma unroll
            for (int j = 0; j < 4; j++) {
                mma16(acc[i][j], aL[i], bH[j]);
                mma16(acc[i][j], aH[i], bL[j]);
                mma16(acc[i][j], aH[i], bH[j]);
            }
        __syncthreads();
    }
    #pragma unroll
    for (int i = 0; i < 2; i++) {
        #pragma unroll
        for (int j = 0; j < 4; j++) {
            int mA = m0 + mw*32 + i*16 + r;
            int nA = n0 + nw*32 + j*8 + cg*2;
            if (mA < M) {
                if (nA   < N) fc(mA, nA,   acc[i][j][0]);
                if (nA+1 < N) fc(mA, nA+1, acc[i][j][1]);
            }
            if (mA + 8 < M) {
                if (nA   < N) fc(mA+8, nA,   acc[i][j][2]);
                if (nA+1 < N) fc(mA+8, nA+1, acc[i][j][3]);
            }
        }
    }
}

// ---------------- attention (3xTF32 — routing-safe) ----------------
__global__ void __launch_bounds__(256, 2) k_gemm_qkv(const float* __restrict__ w) {
    gemm_tc(NTOK, 3*Cn, Cn, blockIdx.y*128, blockIdx.x*64,
        [&] (int m, int k) { return g_tok[(size_t)m*Cn + k]; },
        [&] (int k, int n) { return w[(size_t)k*3*Cn + n]; },
        [&] (int m, int n, float v) { g_qkv[(size_t)m*3*Cn + n] = v; });
}

__global__ void __launch_bounds__(256, 2) k_gemm_scores() {
    int z = blockIdx.z, bI = z >> 3, h = z & 7;
    const float* qb = g_qkv + (size_t)bI*Sn*(3*Cn) + h*Dn;
    const float* kb = qb + Cn;
    float* out = g_scores + (size_t)z*Sn*Sn;
    gemm_tc(Sn, Sn, Dn, blockIdx.y*128, blockIdx.x*64,
        [&] (int m, int k) { return qb[(size_t)m*(3*Cn) + k]; },
        [&] (int k, int n) { return kb[(size_t)n*(3*Cn) + k]; },
        [&] (int m, int n, float v) { out[m*Sn + n] = v; });
}

__global__ void k_softmax() {
    float* p = g_scores + (size_t)blockIdx.x*Sn;
    int tid = threadIdx.x;
    __shared__ float red[128];
    float mx = -1e30f;
    for (int i = tid; i < Sn; i += 128) mx = fmaxf(mx, p[i]);
    red[tid] = mx; __syncthreads();
    for (int o = 64; o > 0; o >>= 1) { if (tid < o) red[tid] = fmaxf(red[tid], red[tid+o]); __syncthreads(); }
    mx = red[0]; __syncthreads();
    float s = 0.f;
    for (int i = tid; i < Sn; i += 128) { float e = __expf(p[i]-mx); p[i] = e; s += e; }
    red[tid] = s; __syncthreads();
    for (int o = 64; o > 0; o >>= 1) { if (tid < o) red[tid] += red[tid+o]; __syncthreads(); }
    float inv = 1.f/red[0];
    for (int i = tid; i < Sn; i += 128) p[i] *= inv;
}

__global__ void __launch_bounds__(256, 2) k_gemm_ctx() {
    int z = blockIdx.z, bI = z >> 3, h = z & 7;
    const float* att = g_scores + (size_t)z*Sn*Sn;
    const float* vb  = g_qkv + (size_t)bI*Sn*(3*Cn) + 2*Cn + h*Dn;
    gemm_tc(Sn, Dn, Sn, blockIdx.y*128, blockIdx.x*64,
        [&] (int m, int k) { return att[(size_t)m*Sn + k]; },
        [&] (int k, int n) { return vb[(size_t)k*(3*Cn) + n]; },
        [&] (int m, int n, float v) {
            g_ctx[((size_t)(bI*Sn + m))*Cn + h*Dn + n] = v;
        });
}

// out-proj + residual: writes tok2 (token-major) and out = x2 ([b,c,s])
__global__ void __launch_bounds__(256, 2) k_gemm_wout(const float* __restrict__ w,
                            const float* __restrict__ x,
                            float* __restrict__ out) {
    gemm_tc(NTOK, Cn, Cn, blockIdx.y*128, blockIdx.x*64,
        [&] (int m, int k) { return g_ctx[(size_t)m*Cn + k]; },
        [&] (int k, int n) { return w[(size_t)k*Cn + n]; },
        [&] (int m, int n, float v) {
            int b = m / Sn, s = m % Sn;
            size_t oi = ((size_t)b*Cn + n)*Sn + s;
            float x2 = x[oi] + v;
            g_tok2[(size_t)m*Cn + n] = x2;
            out[oi] = x2;
        });
}

// ---------------- MoE gate + routing ----------------
__global__ void k_gate(const float* __restrict__ wg, const float* __restrict__ bg) {
    int warp = (blockIdx.x*128 + threadIdx.x) >> 5;
    int lane = threadIdx.x & 31;
    if (warp >= NTOK) return;
    const float* row = g_tok2 + (size_t)warp*Cn;
    float a0 = 0.f, a1 = 0.f, a2 = 0.f;
    for (int c = lane; c < Cn; c += 32) {
        float t = row[c];
        a0 = fmaf(t, wg[c*3+0], a0);
        a1 = fmaf(t, wg[c*3+1], a1);
        a2 = fmaf(t, wg[c*3+2], a2);
    }
    for (int o = 16; o > 0; o >>= 1) {
        a0 += __shfl_down_sync(0xffffffffu, a0, o);
        a1 += __shfl_down_sync(0xffffffffu, a1, o);
        a2 += __shfl_down_sync(0xffffffffu, a2, o);
    }
    if (lane == 0) {
        a0 += bg[0]; a1 += bg[1]; a2 += bg[2];
        int e = 0; float best = a0;
        if (a1 > best) { best = a1; e = 1; }
        if (a2 > best) { best = a2; e = 2; }
        float e0 = __expf(a0-best), e1 = __expf(a1-best), e2 = __expf(a2-best);
        float sum = e0 + e1 + e2;
        float pe = (e == 0 ? e0 : (e == 1 ? e1 : e2)) / sum;
        g_eid[warp] = e; g_mg[warp] = pe;
    }
}

__global__ void k_denom() {
    int i = blockIdx.x*128 + threadIdx.x;
    if (i >= Sn*En) return;
    int s = i / En, e = i % En;
    float acc = 0.f;
    for (int b = 0; b < Bn; b++) { int t = b*Sn + s; if (g_eid[t] == e) acc += g_mg[t]; }
    g_denom[i] = acc + 1e-6f;
}

__global__ void k_scale() {
    int t = blockIdx.x*256 + threadIdx.x;
    if (t >= NTOK) return;
    int s = t % Sn;
    g_gscale[t] = g_mg[t] / g_denom[s*En + g_eid[t]] * (float)Bn;
}

__global__ void k_rinit() {
    int i = blockIdx.x*256 + threadIdx.x;
    if (i < PERMSZ) g_perm[i] = -1;
    if (i < En) { g_count[i] = 0; g_pos[i] = 0; }
}
__global__ void k_rcount() {
    int t = blockIdx.x*256 + threadIdx.x;
    if (t < NTOK) atomicAdd(&g_count[g_eid[t]], 1);
}
__global__ void k_roffs() {
    int a = 0;
    for (int e = 0; e < En; e++) { g_seg[e] = a; a += (g_count[e] + 127) & ~127; }
    g_seg[En] = a;
}
__global__ void k_rscatter() {
    int t = blockIdx.x*256 + threadIdx.x;
    if (t >= NTOK) return;
    int e = g_eid[t];
    int p = atomicAdd(&g_pos[e], 1);
    g_perm[g_seg[e] + p] = t;
}

// ---------------- routed expert FFN (bf16 3-term — post-gate, routing-safe) ----
__global__ void __launch_bounds__(256, 2) k_ffn1(const float* __restrict__ w1, const float* __restrict__ b1) {
    int e = blockIdx.z;
    int cnt = g_count[e];
    int m0 = blockIdx.y*128;
    if (m0 >= cnt) return;
    int base = g_seg[e];
    const float* W = w1 + (size_t)e*Cn*HIDn;
    const float* bias = b1 + e*HIDn;
    gemm_bf(cnt, HIDn, Cn, m0, blockIdx.x*64,
        [&] (int m, int k) { return g_tok2[(size_t)g_perm[base+m]*Cn + k]; },
        [&] (int k, int n) { return W[(size_t)k*HIDn + n]; },
        [&] (int m, int n, float v) {
            float u = v + bias[n];
            g_h1[(size_t)(base+m)*HIDn + n] = 0.5f*u*(1.f + erff(u*0.70710678118654752f));
        });
}

__global__ void __launch_bounds__(256, 2) k_ffn2(const float* __restrict__ w2, const float* __restrict__ b2,
                       float* __restrict__ out) {
    int e = blockIdx.z;
    int cnt = g_count[e];
    int m0 = blockIdx.y*128;
    if (m0 >= cnt) return;
    int base = g_seg[e];
    const float* W = w2 + (size_t)e*HIDn*Cn;
    const float* bias = b2 + e*Cn;
    gemm_bf(cnt, Cn, HIDn, m0, blockIdx.x*64,
        [&] (int m, int k) { return g_h1[(size_t)(base+m)*HIDn + k]; },
        [&] (int k, int n) { return W[(size_t)k*Cn + n]; },
        [&] (int m, int n, float v) {
            int t = g_perm[base+m];
            float g = g_gscale[t];
            int b = t / Sn, s = t % Sn;
            size_t oi = ((size_t)b*Cn + n)*Sn + s;
            out[oi] += g * (v + bias[n]);
        });
}

// ---------------- launch ----------------
extern "C" void kernel_launch(void* const* d_in, const int* in_sizes, int n_in,
                              void* d_out, int out_size) {
    (void)in_sizes; (void)n_in; (void)out_size;
    const float* x      = (const float*)d_in[0];
    const float* gamma  = (const float*)d_in[1];
    const float* beta   = (const float*)d_in[2];
    const float* w_qkv  = (const float*)d_in[3];
    const float* w_out  = (const float*)d_in[4];
    const float* w_gate = (const float*)d_in[5];
    const float* b_gate = (const float*)d_in[6];
    const float* w1     = (const float*)d_in[7];
    const float* b1     = (const float*)d_in[8];
    const float* w2     = (const float*)d_in[9];
    const float* b2     = (const float*)d_in[10];
    float* out = (float*)d_out;

    ln_partial<<<dim3(64, Bn), 256>>>(x);
    ln_final<<<Bn, 64>>>();
    build_tok<<<dim3((Sn+31)/32, Cn/32, Bn), 256>>>(x, gamma, beta);

    k_gemm_qkv<<<dim3((3*Cn)/64, (NTOK+127)/128), 256>>>(w_qkv);        // 36 x 92
    k_gemm_scores<<<dim3(12, 6, Bn*Hn), 256>>>();
    k_softmax<<<Bn*Hn*Sn, 128>>>();
    k_gemm_ctx<<<dim3(2, 6, Bn*Hn), 256>>>();
    k_gemm_wout<<<dim3(Cn/64, (NTOK+127)/128), 256>>>(w_out, x, out);   // 12 x 92

    k_gate<<<(NTOK + 3)/4, 128>>>(w_gate, b_gate);
    k_denom<<<(Sn*En + 127)/128, 128>>>();
    k_scale<<<(NTOK + 255)/256, 256>>>();
    k_rinit<<<(PERMSZ + 255)/256, 256>>>();
    k_rcount<<<(NTOK + 255)/256, 256>>>();
    k_roffs<<<1, 1>>>();
    k_rscatter<<<(NTOK + 255)/256, 256>>>();

    k_ffn1<<<dim3(HIDn/64, (NTOK+127)/128, En), 256>>>(w1, b1);         // 48 x 92 x 3
    k_ffn2<<<dim3(Cn/64, (NTOK+127)/128, En), 256>>>(w2, b2, out);      // 12 x 92 x 3
}